// round 16
// baseline (speedup 1.0000x reference)
#include <cuda_runtime.h>
#include <math.h>

// ContLoss: T=512, B=64, E=1024, N=128
#define TT     512
#define BZ     64
#define EE     1024
#define NNEG   128
#define EPSV   1e-8f
#define INV_TEMP 10.0f   // 1/TEMP, TEMP=0.1

// scratch (zero-initialized __device__ globals)
__device__ float        g_partial[TT];
__device__ unsigned int g_count;

// asm-forced vector load: asm volatile ordering keeps batches back-to-back
// in SASS (ptxas cannot sink them past dependent FMAs). True MLP=8.
__device__ __forceinline__ float4 ldg128(const float4* p) {
    float4 v;
    asm volatile("ld.global.nc.v4.f32 {%0,%1,%2,%3}, [%4];"
                 : "=f"(v.x), "=f"(v.y), "=f"(v.z), "=f"(v.w)
                 : "l"(p));
    return v;
}

#define ACC(v)                                          \
    s0 += (v).x; s1 += (v).y; s2 += (v).z; s3 += (v).w; \
    q0 = fmaf((v).x, (v).x, q0); q1 = fmaf((v).y, (v).y, q1); \
    q2 = fmaf((v).z, (v).z, q2); q3 = fmaf((v).w, (v).w, q3)

// One CTA per t. 256 threads; thread tid owns float4 column tid. MLP=8.
// Anchor/positive loads hoisted above the hot loop so their latency is
// covered by the negative-gather stream instead of exposed at loop exit.
__global__ __launch_bounds__(256, 4) void contloss_fused(
    const int*   __restrict__ index,
    const float* __restrict__ z1,
    const float* __restrict__ z2,
    const int*   __restrict__ neg_s,
    const int*   __restrict__ neg_w,
    float*       __restrict__ out)
{
    const int t   = blockIdx.x;
    const int tid = threadIdx.x;

    __shared__ int sh_off[NNEG];
    if (tid < NNEG) {
        const int j = t * NNEG + tid;
        sh_off[tid] = (neg_s[j] * BZ + neg_w[j]) * (EE / 4);
    }
    __syncthreads();

    const float4* __restrict__ z1v = (const float4*)z1;

    // anchor (orig) and positive (adv) rows — issued BEFORE the hot loop
    const int bidx  = __ldg(index + t);
    const int arow4 = (t * BZ + bidx) * (EE / 4);
    const float4 vo = ldg128(z1v + arow4 + tid);
    const float4 va = ldg128((const float4*)z2 + arow4 + tid);

    float s0 = 0.f, s1 = 0.f, s2 = 0.f, s3 = 0.f;
    float q0 = 0.f, q1 = 0.f, q2 = 0.f, q3 = 0.f;

    for (int n = 0; n < NNEG; n += 8) {
        const float4 v0 = ldg128(z1v + sh_off[n + 0] + tid);
        const float4 v1 = ldg128(z1v + sh_off[n + 1] + tid);
        const float4 v2 = ldg128(z1v + sh_off[n + 2] + tid);
        const float4 v3 = ldg128(z1v + sh_off[n + 3] + tid);
        const float4 v4 = ldg128(z1v + sh_off[n + 4] + tid);
        const float4 v5 = ldg128(z1v + sh_off[n + 5] + tid);
        const float4 v6 = ldg128(z1v + sh_off[n + 6] + tid);
        const float4 v7 = ldg128(z1v + sh_off[n + 7] + tid);

        ACC(v0); ACC(v1); ACC(v2); ACC(v3);
        ACC(v4); ACC(v5); ACC(v6); ACC(v7);
    }

    const float sqrtN = sqrtf((float)NNEG);

    float den = 0.f;
    {
        float o, sm, qq;
        o = vo.x; sm = s0; qq = q0;
        den += expf((o * sm) / (fmaxf(sqrtf(qq), EPSV) * fmaxf(sqrtN * fabsf(o), EPSV)) * INV_TEMP);
        o = vo.y; sm = s1; qq = q1;
        den += expf((o * sm) / (fmaxf(sqrtf(qq), EPSV) * fmaxf(sqrtN * fabsf(o), EPSV)) * INV_TEMP);
        o = vo.z; sm = s2; qq = q2;
        den += expf((o * sm) / (fmaxf(sqrtf(qq), EPSV) * fmaxf(sqrtN * fabsf(o), EPSV)) * INV_TEMP);
        o = vo.w; sm = s3; qq = q3;
        den += expf((o * sm) / (fmaxf(sqrtf(qq), EPSV) * fmaxf(sqrtN * fabsf(o), EPSV)) * INV_TEMP);
    }
    float dotp = vo.x * va.x + vo.y * va.y + vo.z * va.z + vo.w * va.w;
    float na2  = vo.x * vo.x + vo.y * vo.y + vo.z * vo.z + vo.w * vo.w;
    float nb2  = va.x * va.x + va.y * va.y + va.z * va.z + va.w * va.w;

    // deterministic block reduction
    const int lane = tid & 31;
    const int warp = tid >> 5;
    #pragma unroll
    for (int off = 16; off > 0; off >>= 1) {
        den  += __shfl_down_sync(0xffffffffu, den,  off);
        dotp += __shfl_down_sync(0xffffffffu, dotp, off);
        na2  += __shfl_down_sync(0xffffffffu, na2,  off);
        nb2  += __shfl_down_sync(0xffffffffu, nb2,  off);
    }
    __shared__ float r_den[8], r_dot[8], r_na[8], r_nb[8];
    __shared__ bool  sh_last;
    if (lane == 0) {
        r_den[warp] = den; r_dot[warp] = dotp; r_na[warp] = na2; r_nb[warp] = nb2;
    }
    __syncthreads();
    if (tid == 0) {
        float D = 0.f, P = 0.f, A = 0.f, Bv = 0.f;
        #pragma unroll
        for (int w = 0; w < 8; ++w) { D += r_den[w]; P += r_dot[w]; A += r_na[w]; Bv += r_nb[w]; }
        const float pos_cos = P / (fmaxf(sqrtf(A), EPSV) * fmaxf(sqrtf(Bv), EPSV));
        g_partial[t] = logf(D) - pos_cos * INV_TEMP;
        __threadfence();
        const unsigned int done = atomicAdd(&g_count, 1u);
        sh_last = (done == (unsigned int)(gridDim.x - 1));
    }
    __syncthreads();

    // global-last CTA: deterministic tree over the 512 per-t losses
    if (sh_last) {
        __shared__ float sh[256];
        sh[tid] = g_partial[tid] + g_partial[tid + 256];
        __syncthreads();
        #pragma unroll
        for (int s = 128; s > 0; s >>= 1) {
            if (tid < s) sh[tid] += sh[tid + s];
            __syncthreads();
        }
        if (tid == 0) {
            out[0]  = sh[0];
            g_count = 0u;   // reset for next graph replay
        }
    }
}

extern "C" void kernel_launch(void* const* d_in, const int* in_sizes, int n_in,
                              void* d_out, int out_size)
{
    const int*   index = (const int*)  d_in[0];
    const float* z1    = (const float*)d_in[1];
    const float* z2    = (const float*)d_in[2];
    const int*   ns    = (const int*)  d_in[3];
    const int*   nw    = (const int*)  d_in[4];

    contloss_fused<<<TT, 256>>>(index, z1, z2, ns, nw, (float*)d_out);
}